// round 11
// baseline (speedup 1.0000x reference)
#include <cuda_runtime.h>
#include <math.h>

// ---------------- problem constants ----------------
#define Bsz 64
#define Tt  512
#define Dd  512
#define Hh  512
#define G4  2048           // 4*H
#define NCTA 128           // persistent CTAs for recurrence (<=148 SMs, 1/SM)

// ---------------- device scratch (no allocs allowed) ----------------
__device__ float g_Wx[Dd * G4];            // packed [D][4H], col n = gate*512+h
__device__ float g_Wh[Hh * G4];            // packed [H][4H]
__device__ float g_bias[G4];
__device__ float g_Xg[(size_t)Tt * Bsz * G4];  // [t][b][4H], 268 MB
__device__ float g_hbuf[2][Hh * Bsz];      // h[buf][k*64 + b]
__device__ unsigned int g_barcnt = 0;
__device__ unsigned int g_bargen = 0;

// ---------------- software grid barrier (all 128 CTAs co-resident) ----------
__device__ __forceinline__ void grid_barrier()
{
    __syncthreads();
    if (threadIdx.x == 0) {
        unsigned int gen = ((volatile unsigned int*)&g_bargen)[0];
        __threadfence();
        if (atomicInc(&g_barcnt, NCTA - 1) == NCTA - 1) {
            atomicAdd(&g_bargen, 1);            // release
        } else {
            while (((volatile unsigned int*)&g_bargen)[0] == gen) { }
        }
        __threadfence();
    }
    __syncthreads();
}

__device__ __forceinline__ float sigmoidf_(float x) { return 1.0f / (1.0f + __expf(-x)); }
// tanh via fast exp: tanh(x) = 1 - 2/(e^{2x}+1). |err| ~1e-7 rel, fine vs 1e-3.
__device__ __forceinline__ float tanhf_(float x)
{
    return 1.0f - 2.0f / (__expf(2.0f * x) + 1.0f);
}

// ---------------- pack weights into fused [K][4H] layout ----------------
__global__ void pack_kernel(
    const float* __restrict__ wxi, const float* __restrict__ whi, const float* __restrict__ bi,
    const float* __restrict__ wxf, const float* __restrict__ whf, const float* __restrict__ bff,
    const float* __restrict__ wxo, const float* __restrict__ who, const float* __restrict__ bo,
    const float* __restrict__ wxc, const float* __restrict__ whc, const float* __restrict__ bc)
{
    int idx = blockIdx.x * blockDim.x + threadIdx.x;
    if (idx >= Dd * Hh) return;
    int d = idx >> 9;
    int h = idx & 511;
    const float* wx[4] = {wxi, wxf, wxo, wxc};
    const float* wh[4] = {whi, whf, who, whc};
    const float* bs[4] = {bi,  bff, bo,  bc};
#pragma unroll
    for (int g = 0; g < 4; g++) {
        g_Wx[d * G4 + g * Hh + h] = wx[g][idx];
        g_Wh[d * G4 + g * Hh + h] = wh[g][idx];
    }
    if (d == 0) {
#pragma unroll
        for (int g = 0; g < 4; g++) g_bias[g * Hh + h] = bs[g][h];
    }
}

// ---------------- phase 1: Xg = X @ Wx + b  (SGEMM 32768x2048x512) -------
#define BM 128
#define BN 128
#define BK 16

__global__ void __launch_bounds__(256, 2) xg_gemm(const float* __restrict__ A)
{
    __shared__ float As[2][BK][BM];
    __shared__ float Bs[2][BK][BN];
    const int tid  = threadIdx.x;
    const int bx   = blockIdx.x;   // N tiles: 0..15
    const int by   = blockIdx.y;   // M tiles: 0..255
    const int row0 = by * BM;
    const int col0 = bx * BN;

    const int tx = tid & 15;
    const int ty = tid >> 4;

    const int i0 = tid * 2;
    const int i1 = tid * 2 + 1;
    const int a_ar0 = i0 >> 2, a_ac0 = (i0 & 3) * 4;
    const int a_ar1 = i1 >> 2, a_ac1 = (i1 & 3) * 4;
    const int b_br0 = i0 >> 5, b_bc0 = (i0 & 31) * 4;
    const int b_br1 = i1 >> 5, b_bc1 = (i1 & 31) * 4;

    float4 av0, av1, bv0, bv1;
    av0 = *(const float4*)&A[(size_t)(row0 + a_ar0) * Dd + a_ac0];
    av1 = *(const float4*)&A[(size_t)(row0 + a_ar1) * Dd + a_ac1];
    bv0 = *(const float4*)&g_Wx[(size_t)b_br0 * G4 + col0 + b_bc0];
    bv1 = *(const float4*)&g_Wx[(size_t)b_br1 * G4 + col0 + b_bc1];
    As[0][a_ac0+0][a_ar0] = av0.x; As[0][a_ac0+1][a_ar0] = av0.y;
    As[0][a_ac0+2][a_ar0] = av0.z; As[0][a_ac0+3][a_ar0] = av0.w;
    As[0][a_ac1+0][a_ar1] = av1.x; As[0][a_ac1+1][a_ar1] = av1.y;
    As[0][a_ac1+2][a_ar1] = av1.z; As[0][a_ac1+3][a_ar1] = av1.w;
    *(float4*)&Bs[0][b_br0][b_bc0] = bv0;
    *(float4*)&Bs[0][b_br1][b_bc1] = bv1;
    __syncthreads();

    float acc[8][8];
#pragma unroll
    for (int i = 0; i < 8; i++)
#pragma unroll
        for (int j = 0; j < 8; j++) acc[i][j] = 0.f;

    const int NKT = Dd / BK;   // 32
    for (int kt = 0; kt < NKT; kt++) {
        const int cur = kt & 1, nxt = cur ^ 1;
        if (kt + 1 < NKT) {
            const int k0 = (kt + 1) * BK;
            av0 = *(const float4*)&A[(size_t)(row0 + a_ar0) * Dd + k0 + a_ac0];
            av1 = *(const float4*)&A[(size_t)(row0 + a_ar1) * Dd + k0 + a_ac1];
            bv0 = *(const float4*)&g_Wx[(size_t)(k0 + b_br0) * G4 + col0 + b_bc0];
            bv1 = *(const float4*)&g_Wx[(size_t)(k0 + b_br1) * G4 + col0 + b_bc1];
        }
#pragma unroll
        for (int k = 0; k < BK; k++) {
            float4 a0 = *(const float4*)&As[cur][k][ty * 4];
            float4 a1 = *(const float4*)&As[cur][k][64 + ty * 4];
            float4 b0 = *(const float4*)&Bs[cur][k][tx * 4];
            float4 b1 = *(const float4*)&Bs[cur][k][64 + tx * 4];
            float ra[8] = {a0.x, a0.y, a0.z, a0.w, a1.x, a1.y, a1.z, a1.w};
            float rb[8] = {b0.x, b0.y, b0.z, b0.w, b1.x, b1.y, b1.z, b1.w};
#pragma unroll
            for (int i = 0; i < 8; i++)
#pragma unroll
                for (int j = 0; j < 8; j++)
                    acc[i][j] += ra[i] * rb[j];
        }
        if (kt + 1 < NKT) {
            As[nxt][a_ac0+0][a_ar0] = av0.x; As[nxt][a_ac0+1][a_ar0] = av0.y;
            As[nxt][a_ac0+2][a_ar0] = av0.z; As[nxt][a_ac0+3][a_ar0] = av0.w;
            As[nxt][a_ac1+0][a_ar1] = av1.x; As[nxt][a_ac1+1][a_ar1] = av1.y;
            As[nxt][a_ac1+2][a_ar1] = av1.z; As[nxt][a_ac1+3][a_ar1] = av1.w;
            *(float4*)&Bs[nxt][b_br0][b_bc0] = bv0;
            *(float4*)&Bs[nxt][b_br1][b_bc1] = bv1;
            __syncthreads();
        }
    }

    // epilogue: add bias, remap row r=(b*512+t) -> Xg row (t*64+b)
#pragma unroll
    for (int i = 0; i < 8; i++) {
        const int mr  = row0 + ((i < 4) ? (ty * 4 + i) : (64 + ty * 4 + (i - 4)));
        const int orow = (mr & (Tt - 1)) * Bsz + (mr >> 9);
#pragma unroll
        for (int jh = 0; jh < 2; jh++) {
            const int c = col0 + jh * 64 + tx * 4;
            float4 bv = *(const float4*)&g_bias[c];
            float4 v;
            v.x = acc[i][jh * 4 + 0] + bv.x;
            v.y = acc[i][jh * 4 + 1] + bv.y;
            v.z = acc[i][jh * 4 + 2] + bv.z;
            v.w = acc[i][jh * 4 + 3] + bv.w;
            *(float4*)&g_Xg[(size_t)orow * G4 + c] = v;
        }
    }
}

// ---------------- phase 2: persistent recurrence kernel ----------------
// 128 CTAs x 256 threads, CTA owns 4 hidden cols (16 gate cols).
// h is read straight from L2 (__ldcg) inside the FMA loop — no staging phase.
// SMEM: W slice 32KB (resident all steps) + reduction 33KB + out gather 1KB.
#define SMEM_W_FLOATS   (512 * 16)
#define SMEM_RED_FLOATS (8 * 32 * 33)
#define SMEM_OUT_FLOATS (64 * 4)
#define REC_SMEM_BYTES  ((SMEM_W_FLOATS + SMEM_RED_FLOATS + SMEM_OUT_FLOATS) * 4)

__global__ void __launch_bounds__(256, 1) lstm_rec(float* __restrict__ out)
{
    extern __shared__ float sm[];
    float* sh_w   = sm;                              // [512][16], cc = jj*4+gate
    float* sh_red = sm + SMEM_W_FLOATS;              // [(ks*32+base)][33]
    float* sh_out = sh_red + SMEM_RED_FLOATS;        // [64 b][4 jj]

    const int tid = threadIdx.x;
    const int cta = blockIdx.x;
    const int j0  = cta * 4;

    // load persistent W_h slice (once)
    for (int i = tid; i < 512 * 16; i += 256) {
        const int k = i >> 4, cc = i & 15;
        const int jj = cc >> 2, gate = cc & 3;
        sh_w[i] = g_Wh[(size_t)k * G4 + gate * Hh + j0 + jj];
    }

    // GEMM thread decomposition: K split 8, 8b x 4cc register tile
    const int ks   = tid >> 5;        // 0..7
    const int base = tid & 31;        // 0..31
    const int bg   = base >> 2;       // 0..7  -> b0 = bg*8
    const int cg   = base & 3;        // jj group (4 gate cols)

    // epilogue decomposition: thread <-> (batch, hidden col)
    const int e_b    = tid & 63;
    const int e_jj   = tid >> 6;      // 0..3
    const int e_bg   = e_b >> 3, e_bb = e_b & 7;
    const int e_base = e_bg * 4 + e_jj;
    const int jcol   = j0 + e_jj;

    float c_state = 0.f;

    // ---- step 0: h = 0, so g = Xg[0] only ----
    {
        float gg[4];
#pragma unroll
        for (int gate = 0; gate < 4; gate++)
            gg[gate] = g_Xg[(size_t)e_b * G4 + gate * Hh + jcol];
        const float I = sigmoidf_(gg[0]);
        const float F = sigmoidf_(gg[1]);
        const float O = sigmoidf_(gg[2]);
        const float Cd = tanhf_(gg[3]);
        c_state = F * c_state + I * Cd;
        const float hval = O * tanhf_(c_state);
        g_hbuf[0][jcol * Bsz + e_b] = hval;
        sh_out[e_b * 4 + e_jj] = hval;
    }
    __syncthreads();
    if (tid < 64)   // coalesced 16B stores along hidden dim
        *(float4*)&out[(size_t)tid * (Tt * Hh) + j0] = *(const float4*)&sh_out[tid * 4];
    grid_barrier();

    const float4* sh_w4 = (const float4*)sh_w;
    const int kb = ks * 64;

    for (int t = 1; t < Tt; t++) {
        // prefetch this step's Xg (DRAM) so its latency hides under the GEMM
        float xg_pre[4];
#pragma unroll
        for (int gate = 0; gate < 4; gate++)
            xg_pre[gate] = __ldg(&g_Xg[((size_t)t * Bsz + e_b) * G4 + gate * Hh + jcol]);

        // partial GEMM on K slice [ks*64, ks*64+64), h read straight from L2
        const float4* hg = (const float4*)g_hbuf[(t + 1) & 1];
        float acc[8][4];
#pragma unroll
        for (int b = 0; b < 8; b++)
#pragma unroll
            for (int c = 0; c < 4; c++) acc[b][c] = 0.f;

#pragma unroll 4
        for (int kk = 0; kk < 64; kk++) {
            const int k = kb + kk;
            const float4 w  = sh_w4[k * 4 + cg];
            const float4 h0 = __ldcg(&hg[k * 16 + bg * 2]);
            const float4 h1 = __ldcg(&hg[k * 16 + bg * 2 + 1]);
            const float hv[8] = {h0.x, h0.y, h0.z, h0.w, h1.x, h1.y, h1.z, h1.w};
#pragma unroll
            for (int b = 0; b < 8; b++) {
                acc[b][0] += hv[b] * w.x;
                acc[b][1] += hv[b] * w.y;
                acc[b][2] += hv[b] * w.z;
                acc[b][3] += hv[b] * w.w;
            }
        }

        // write partials (padded rows: conflict-free)
        float* myred = &sh_red[(ks * 32 + base) * 33];
#pragma unroll
        for (int b = 0; b < 8; b++)
#pragma unroll
            for (int c = 0; c < 4; c++)
                myred[b * 4 + c] = acc[b][c];
        __syncthreads();

        // reduce 8 K-partials + prefetched Xg, then gate math
        float gg[4];
#pragma unroll
        for (int gate = 0; gate < 4; gate++) {
            float s = xg_pre[gate];
#pragma unroll
            for (int p = 0; p < 8; p++)
                s += sh_red[(p * 32 + e_base) * 33 + e_bb * 4 + gate];
            gg[gate] = s;
        }
        const float I = sigmoidf_(gg[0]);
        const float F = sigmoidf_(gg[1]);
        const float O = sigmoidf_(gg[2]);
        const float Cd = tanhf_(gg[3]);
        c_state = F * c_state + I * Cd;
        const float hval = O * tanhf_(c_state);
        g_hbuf[t & 1][jcol * Bsz + e_b] = hval;   // coalesced along batch
        sh_out[e_b * 4 + e_jj] = hval;
        __syncthreads();
        if (tid < 64)
            *(float4*)&out[(size_t)tid * (Tt * Hh) + (size_t)t * Hh + j0] =
                *(const float4*)&sh_out[tid * 4];

        grid_barrier();
    }
}

// ---------------- launch ----------------
extern "C" void kernel_launch(void* const* d_in, const int* in_sizes, int n_in,
                              void* d_out, int out_size)
{
    const float* X   = (const float*)d_in[0];
    const float* wxi = (const float*)d_in[1];
    const float* whi = (const float*)d_in[2];
    const float* bi  = (const float*)d_in[3];
    const float* wxf = (const float*)d_in[4];
    const float* whf = (const float*)d_in[5];
    const float* bff = (const float*)d_in[6];
    const float* wxo = (const float*)d_in[7];
    const float* who = (const float*)d_in[8];
    const float* bo  = (const float*)d_in[9];
    const float* wxc = (const float*)d_in[10];
    const float* whc = (const float*)d_in[11];
    const float* bc  = (const float*)d_in[12];
    float* out = (float*)d_out;

    pack_kernel<<<(Dd * Hh + 255) / 256, 256>>>(wxi, whi, bi, wxf, whf, bff,
                                                wxo, who, bo, wxc, whc, bc);

    dim3 grid(G4 / BN, (Bsz * Tt) / BM);   // (16, 256)
    xg_gemm<<<grid, 256>>>(X);

    cudaFuncSetAttribute(lstm_rec, cudaFuncAttributeMaxDynamicSharedMemorySize,
                         REC_SMEM_BYTES);
    lstm_rec<<<NCTA, 256, REC_SMEM_BYTES>>>(out);
}

// round 13
// speedup vs baseline: 1.3530x; 1.3530x over previous
#include <cuda_runtime.h>
#include <math.h>
#include <stdint.h>

// ---------------- problem constants ----------------
#define Bsz 64
#define Tt  512
#define Dd  512
#define Hh  512
#define G4  2048           // 4*H
#define NCTA 128           // persistent CTAs for recurrence (<=148 SMs, 1/SM)

// ---------------- device scratch (no allocs allowed) ----------------
__device__ __align__(16) float g_Wx[Dd * G4];   // packed [D][4H], col n = gate*512+h
__device__ __align__(16) float g_Wh[Hh * G4];   // packed [H][4H]
__device__ __align__(16) float g_bias[G4];
__device__ __align__(16) float g_Xg[(size_t)Tt * Bsz * G4];  // [t][b][4H]
__device__ __align__(16) float g_hbuf[2][Hh * Bsz];          // h[buf][k*64 + b]
__device__ unsigned int g_barcnt = 0;
__device__ unsigned int g_bargen = 0;

// ---------------- software grid barrier (all 128 CTAs co-resident) ----------
__device__ __forceinline__ void grid_barrier()
{
    __syncthreads();
    if (threadIdx.x == 0) {
        unsigned int gen = ((volatile unsigned int*)&g_bargen)[0];
        __threadfence();
        if (atomicInc(&g_barcnt, NCTA - 1) == NCTA - 1) {
            atomicAdd(&g_bargen, 1);            // release
        } else {
            while (((volatile unsigned int*)&g_bargen)[0] == gen) { }
        }
        __threadfence();
    }
    __syncthreads();
}

__device__ __forceinline__ float sigmoidf_(float x) { return 1.0f / (1.0f + __expf(-x)); }
__device__ __forceinline__ float tanhf_(float x)
{
    return 1.0f - 2.0f / (__expf(2.0f * x) + 1.0f);
}

// ---------------- cp.async helpers ----------------
__device__ __forceinline__ void cp_async16(uint32_t smem_addr, const void* gptr)
{
    asm volatile("cp.async.cg.shared.global [%0], [%1], 16;"
                 :: "r"(smem_addr), "l"(gptr) : "memory");
}
__device__ __forceinline__ void cp_commit()
{
    asm volatile("cp.async.commit_group;" ::: "memory");
}
template<int N> __device__ __forceinline__ void cp_wait()
{
    asm volatile("cp.async.wait_group %0;" :: "n"(N) : "memory");
}
__device__ __forceinline__ uint32_t smem_u32(const void* p)
{
    return (uint32_t)__cvta_generic_to_shared(p);
}

// ---------------- pack weights into fused [K][4H] layout ----------------
__global__ void pack_kernel(
    const float* __restrict__ wxi, const float* __restrict__ whi, const float* __restrict__ bi,
    const float* __restrict__ wxf, const float* __restrict__ whf, const float* __restrict__ bff,
    const float* __restrict__ wxo, const float* __restrict__ who, const float* __restrict__ bo,
    const float* __restrict__ wxc, const float* __restrict__ whc, const float* __restrict__ bc)
{
    int idx = blockIdx.x * blockDim.x + threadIdx.x;
    if (idx >= Dd * Hh) return;
    int d = idx >> 9;
    int h = idx & 511;
    const float* wx[4] = {wxi, wxf, wxo, wxc};
    const float* wh[4] = {whi, whf, who, whc};
    const float* bs[4] = {bi,  bff, bo,  bc};
#pragma unroll
    for (int g = 0; g < 4; g++) {
        g_Wx[d * G4 + g * Hh + h] = wx[g][idx];
        g_Wh[d * G4 + g * Hh + h] = wh[g][idx];
    }
    if (d == 0) {
#pragma unroll
        for (int g = 0; g < 4; g++) g_bias[g * Hh + h] = bs[g][h];
    }
}

// ---------------- phase 1: Xg = X @ Wx + b  (SGEMM 32768x2048x512) -------
#define BM 128
#define BN 128
#define BK 16

__global__ void __launch_bounds__(256, 2) xg_gemm(const float* __restrict__ A)
{
    __shared__ float As[2][BK][BM];
    __shared__ float Bs[2][BK][BN];
    const int tid  = threadIdx.x;
    const int bx   = blockIdx.x;
    const int by   = blockIdx.y;
    const int row0 = by * BM;
    const int col0 = bx * BN;

    const int tx = tid & 15;
    const int ty = tid >> 4;

    const int i0 = tid * 2;
    const int i1 = tid * 2 + 1;
    const int a_ar0 = i0 >> 2, a_ac0 = (i0 & 3) * 4;
    const int a_ar1 = i1 >> 2, a_ac1 = (i1 & 3) * 4;
    const int b_br0 = i0 >> 5, b_bc0 = (i0 & 31) * 4;
    const int b_br1 = i1 >> 5, b_bc1 = (i1 & 31) * 4;

    float4 av0, av1, bv0, bv1;
    av0 = *(const float4*)&A[(size_t)(row0 + a_ar0) * Dd + a_ac0];
    av1 = *(const float4*)&A[(size_t)(row0 + a_ar1) * Dd + a_ac1];
    bv0 = *(const float4*)&g_Wx[(size_t)b_br0 * G4 + col0 + b_bc0];
    bv1 = *(const float4*)&g_Wx[(size_t)b_br1 * G4 + col0 + b_bc1];
    As[0][a_ac0+0][a_ar0] = av0.x; As[0][a_ac0+1][a_ar0] = av0.y;
    As[0][a_ac0+2][a_ar0] = av0.z; As[0][a_ac0+3][a_ar0] = av0.w;
    As[0][a_ac1+0][a_ar1] = av1.x; As[0][a_ac1+1][a_ar1] = av1.y;
    As[0][a_ac1+2][a_ar1] = av1.z; As[0][a_ac1+3][a_ar1] = av1.w;
    *(float4*)&Bs[0][b_br0][b_bc0] = bv0;
    *(float4*)&Bs[0][b_br1][b_bc1] = bv1;
    __syncthreads();

    float acc[8][8];
#pragma unroll
    for (int i = 0; i < 8; i++)
#pragma unroll
        for (int j = 0; j < 8; j++) acc[i][j] = 0.f;

    const int NKT = Dd / BK;   // 32
    for (int kt = 0; kt < NKT; kt++) {
        const int cur = kt & 1, nxt = cur ^ 1;
        if (kt + 1 < NKT) {
            const int k0 = (kt + 1) * BK;
            av0 = *(const float4*)&A[(size_t)(row0 + a_ar0) * Dd + k0 + a_ac0];
            av1 = *(const float4*)&A[(size_t)(row0 + a_ar1) * Dd + k0 + a_ac1];
            bv0 = *(const float4*)&g_Wx[(size_t)(k0 + b_br0) * G4 + col0 + b_bc0];
            bv1 = *(const float4*)&g_Wx[(size_t)(k0 + b_br1) * G4 + col0 + b_bc1];
        }
#pragma unroll
        for (int k = 0; k < BK; k++) {
            float4 a0 = *(const float4*)&As[cur][k][ty * 4];
            float4 a1 = *(const float4*)&As[cur][k][64 + ty * 4];
            float4 b0 = *(const float4*)&Bs[cur][k][tx * 4];
            float4 b1 = *(const float4*)&Bs[cur][k][64 + tx * 4];
            float ra[8] = {a0.x, a0.y, a0.z, a0.w, a1.x, a1.y, a1.z, a1.w};
            float rb[8] = {b0.x, b0.y, b0.z, b0.w, b1.x, b1.y, b1.z, b1.w};
#pragma unroll
            for (int i = 0; i < 8; i++)
#pragma unroll
                for (int j = 0; j < 8; j++)
                    acc[i][j] += ra[i] * rb[j];
        }
        if (kt + 1 < NKT) {
            As[nxt][a_ac0+0][a_ar0] = av0.x; As[nxt][a_ac0+1][a_ar0] = av0.y;
            As[nxt][a_ac0+2][a_ar0] = av0.z; As[nxt][a_ac0+3][a_ar0] = av0.w;
            As[nxt][a_ac1+0][a_ar1] = av1.x; As[nxt][a_ac1+1][a_ar1] = av1.y;
            As[nxt][a_ac1+2][a_ar1] = av1.z; As[nxt][a_ac1+3][a_ar1] = av1.w;
            *(float4*)&Bs[nxt][b_br0][b_bc0] = bv0;
            *(float4*)&Bs[nxt][b_br1][b_bc1] = bv1;
            __syncthreads();
        }
    }

    // epilogue: add bias, remap row r=(b*512+t) -> Xg row (t*64+b)
#pragma unroll
    for (int i = 0; i < 8; i++) {
        const int mr  = row0 + ((i < 4) ? (ty * 4 + i) : (64 + ty * 4 + (i - 4)));
        const int orow = (mr & (Tt - 1)) * Bsz + (mr >> 9);
#pragma unroll
        for (int jh = 0; jh < 2; jh++) {
            const int c = col0 + jh * 64 + tx * 4;
            float4 bv = *(const float4*)&g_bias[c];
            float4 v;
            v.x = acc[i][jh * 4 + 0] + bv.x;
            v.y = acc[i][jh * 4 + 1] + bv.y;
            v.z = acc[i][jh * 4 + 2] + bv.z;
            v.w = acc[i][jh * 4 + 3] + bv.w;
            *(float4*)&g_Xg[(size_t)orow * G4 + c] = v;
        }
    }
}

// ---------------- phase 2: persistent recurrence kernel ----------------
// 128 CTAs x 256 threads, CTA owns 4 hidden cols (16 gate cols).
// Warp w (=ks) consumes only h rows [64w, 64w+64): per-warp cp.async pipeline
// stages its 16KB chunk in 4 sub-chunks, overlapped with the FMA stream.
#define SMEM_W_FLOATS   (512 * 16)          // 32 KB
#define SMEM_H_FLOATS   (512 * 64)          // 128 KB (8 warp regions of 16KB)
#define SMEM_RED_FLOATS (8 * 32 * 33)       // 33.8 KB (33-skew, scalar access)
#define SMEM_XG_FLOATS  (64 * 16)           // 4 KB
#define SMEM_OUT_FLOATS (64 * 4)            // 1 KB
#define REC_SMEM_BYTES  ((SMEM_W_FLOATS + SMEM_H_FLOATS + SMEM_RED_FLOATS + \
                          SMEM_XG_FLOATS + SMEM_OUT_FLOATS) * 4)

__global__ void __launch_bounds__(256, 1) lstm_rec(float* __restrict__ out)
{
    extern __shared__ float sm[];
    float* sh_w   = sm;                              // [512][16], cc = jj*4+gate
    float* sh_h   = sm + SMEM_W_FLOATS;              // 8 x [64 k'][64 b]
    float* sh_red = sh_h + SMEM_H_FLOATS;            // [(ks*32+lane)][33]
    float* sh_xg  = sh_red + SMEM_RED_FLOATS;        // [64 b][16 = gate*4+jj]
    float* sh_out = sh_xg + SMEM_XG_FLOATS;          // [64 b][4 jj]

    const int tid  = threadIdx.x;
    const int cta  = blockIdx.x;
    const int j0   = cta * 4;
    const int lane = tid & 31;

    // load persistent W_h slice (once)
    for (int i = tid; i < 512 * 16; i += 256) {
        const int k = i >> 4, cc = i & 15;
        const int jj = cc >> 2, gate = cc & 3;
        sh_w[i] = g_Wh[(size_t)k * G4 + gate * Hh + j0 + jj];
    }

    // GEMM thread decomposition: warp ks owns K chunk [ks*64, ks*64+64)
    const int ks   = tid >> 5;        // 0..7 (= warp id)
    const int bg   = lane >> 2;       // 0..7  -> b0 = bg*8
    const int cg   = lane & 3;        // jj group (4 gate cols)
    const int kb   = ks * 64;

    // this warp's SMEM h region
    float*        sh_hw   = sh_h + ks * (64 * 64);
    const float4* sh_hw4  = (const float4*)sh_hw;
    const uint32_t dst0   = smem_u32(sh_hw);

    // epilogue decomposition: thread <-> (batch, hidden col)
    const int e_b    = tid & 63;
    const int e_jj   = tid >> 6;      // 0..3
    const int e_bg   = e_b >> 3, e_bb = e_b & 7;
    const int e_base = e_bg * 4 + e_jj;
    const int jcol   = j0 + e_jj;

    float c_state = 0.f;

    // ---- step 0: h = 0, so g = Xg[0] only ----
    {
        float gg[4];
#pragma unroll
        for (int gate = 0; gate < 4; gate++)
            gg[gate] = g_Xg[(size_t)e_b * G4 + gate * Hh + jcol];
        const float I = sigmoidf_(gg[0]);
        const float F = sigmoidf_(gg[1]);
        const float O = sigmoidf_(gg[2]);
        const float Cd = tanhf_(gg[3]);
        c_state = F * c_state + I * Cd;
        const float hval = O * tanhf_(c_state);
        g_hbuf[0][jcol * Bsz + e_b] = hval;
        sh_out[e_b * 4 + e_jj] = hval;
    }
    __syncthreads();
    if (tid < 64)
        *(float4*)&out[(size_t)tid * (Tt * Hh) + j0] = *(const float4*)&sh_out[tid * 4];
    grid_barrier();

    const float4* sh_w4 = (const float4*)sh_w;

    for (int t = 1; t < Tt; t++) {
        // ---- Xg prefetch: coalesced float4 loads, redistributed via SMEM ----
        float4 xg4[4];
        if (tid < 64) {
#pragma unroll
            for (int g = 0; g < 4; g++)
                xg4[g] = __ldg((const float4*)&g_Xg[((size_t)t * Bsz + tid) * G4 +
                                                    g * Hh + j0]);
        }

        // ---- warp-local cp.async pipeline: 4 sub-chunks of 4KB ----
        const float* hsrc = g_hbuf[(t + 1) & 1] + kb * 64;
#pragma unroll
        for (int j = 0; j < 8; j++)
            cp_async16(dst0 + (j * 32 + lane) * 16, hsrc + (j * 32 + lane) * 4);
        cp_commit();
#pragma unroll
        for (int j = 8; j < 16; j++)
            cp_async16(dst0 + (j * 32 + lane) * 16, hsrc + (j * 32 + lane) * 4);
        cp_commit();

        float acc[8][4];
#pragma unroll
        for (int b = 0; b < 8; b++)
#pragma unroll
            for (int c = 0; c < 4; c++) acc[b][c] = 0.f;

#pragma unroll
        for (int s = 0; s < 4; s++) {
            if (s < 2) {
                const int jb = (s + 2) * 8;
#pragma unroll
                for (int j = 0; j < 8; j++)
                    cp_async16(dst0 + ((jb + j) * 32 + lane) * 16,
                               hsrc + ((jb + j) * 32 + lane) * 4);
                cp_commit();
            }
            if      (s == 0) cp_wait<2>();
            else if (s == 1) cp_wait<2>();
            else if (s == 2) cp_wait<1>();
            else             cp_wait<0>();
            __syncwarp();

#pragma unroll
            for (int kk = 0; kk < 16; kk++) {
                const int kl = s * 16 + kk;          // local k in warp chunk
                const float4 w  = sh_w4[(kb + kl) * 4 + cg];
                const float4 h0 = sh_hw4[kl * 16 + bg * 2];
                const float4 h1 = sh_hw4[kl * 16 + bg * 2 + 1];
                const float hv[8] = {h0.x, h0.y, h0.z, h0.w, h1.x, h1.y, h1.z, h1.w};
#pragma unroll
                for (int b = 0; b < 8; b++) {
                    acc[b][0] += hv[b] * w.x;
                    acc[b][1] += hv[b] * w.y;
                    acc[b][2] += hv[b] * w.z;
                    acc[b][3] += hv[b] * w.w;
                }
            }
        }

        // write partials — SCALAR stores into 33-skewed rows (conflict-free;
        // 132B row stride is NOT 16B-aligned, so no float4 here)
        float* myred = &sh_red[(ks * 32 + lane) * 33];
#pragma unroll
        for (int b = 0; b < 8; b++)
#pragma unroll
            for (int c = 0; c < 4; c++)
                myred[b * 4 + c] = acc[b][c];
        // park prefetched Xg in SMEM for the epilogue threads
        if (tid < 64) {
#pragma unroll
            for (int g = 0; g < 4; g++)
                *(float4*)&sh_xg[tid * 16 + g * 4] = xg4[g];
        }
        __syncthreads();

        // reduce 8 K-partials + Xg, then gate math: thread owns (e_b, jcol)
        float gg[4];
#pragma unroll
        for (int gate = 0; gate < 4; gate++) {
            float ss = sh_xg[e_b * 16 + gate * 4 + e_jj];
#pragma unroll
            for (int p = 0; p < 8; p++)
                ss += sh_red[(p * 32 + e_base) * 33 + e_bb * 4 + gate];
            gg[gate] = ss;
        }
        const float I = sigmoidf_(gg[0]);
        const float F = sigmoidf_(gg[1]);
        const float O = sigmoidf_(gg[2]);
        const float Cd = tanhf_(gg[3]);
        c_state = F * c_state + I * Cd;
        const float hval = O * tanhf_(c_state);
        g_hbuf[t & 1][jcol * Bsz + e_b] = hval;   // coalesced along batch
        sh_out[e_b * 4 + e_jj] = hval;
        __syncthreads();
        if (tid < 64)
            *(float4*)&out[(size_t)tid * (Tt * Hh) + (size_t)t * Hh + j0] =
                *(const float4*)&sh_out[tid * 4];

        grid_barrier();
    }
}

// ---------------- launch ----------------
extern "C" void kernel_launch(void* const* d_in, const int* in_sizes, int n_in,
                              void* d_out, int out_size)
{
    const float* X   = (const float*)d_in[0];
    const float* wxi = (const float*)d_in[1];
    const float* whi = (const float*)d_in[2];
    const float* bi  = (const float*)d_in[3];
    const float* wxf = (const float*)d_in[4];
    const float* whf = (const float*)d_in[5];
    const float* bff = (const float*)d_in[6];
    const float* wxo = (const float*)d_in[7];
    const float* who = (const float*)d_in[8];
    const float* bo  = (const float*)d_in[9];
    const float* wxc = (const float*)d_in[10];
    const float* whc = (const float*)d_in[11];
    const float* bc  = (const float*)d_in[12];
    float* out = (float*)d_out;

    pack_kernel<<<(Dd * Hh + 255) / 256, 256>>>(wxi, whi, bi, wxf, whf, bff,
                                                wxo, who, bo, wxc, whc, bc);

    dim3 grid(G4 / BN, (Bsz * Tt) / BM);   // (16, 256)
    xg_gemm<<<grid, 256>>>(X);

    cudaFuncSetAttribute(lstm_rec, cudaFuncAttributeMaxDynamicSharedMemorySize,
                         REC_SMEM_BYTES);
    lstm_rec<<<NCTA, 256, REC_SMEM_BYTES>>>(out);
}

// round 14
// speedup vs baseline: 1.4199x; 1.0495x over previous
#include <cuda_runtime.h>
#include <math.h>
#include <stdint.h>

// ---------------- problem constants ----------------
#define Bsz 64
#define Tt  512
#define Dd  512
#define Hh  512
#define G4  2048           // 4*H
#define NCTA 128           // persistent CTAs for recurrence (<=148 SMs, 1/SM)

// ---------------- device scratch (no allocs allowed) ----------------
__device__ __align__(16) float g_Wx[Dd * G4];   // packed [D][4H], col n = gate*512+h
__device__ __align__(16) float g_Wh[Hh * G4];   // packed [H][4H]
__device__ __align__(16) float g_bias[G4];
__device__ __align__(16) float g_Xg[(size_t)Tt * Bsz * G4];  // [t][b][4H]
__device__ __align__(16) float g_hbuf[2][Hh * Bsz];          // h[buf][k*64 + b]
__device__ unsigned int g_barcnt = 0;
__device__ unsigned int g_bargen = 0;

// ---------------- software grid barrier (all 128 CTAs co-resident) ----------
__device__ __forceinline__ void grid_barrier()
{
    __syncthreads();
    if (threadIdx.x == 0) {
        unsigned int gen = ((volatile unsigned int*)&g_bargen)[0];
        __threadfence();
        if (atomicInc(&g_barcnt, NCTA - 1) == NCTA - 1) {
            atomicAdd(&g_bargen, 1);            // release
        } else {
            while (((volatile unsigned int*)&g_bargen)[0] == gen) { }
        }
        __threadfence();
    }
    __syncthreads();
}

__device__ __forceinline__ float sigmoidf_(float x) { return 1.0f / (1.0f + __expf(-x)); }
__device__ __forceinline__ float tanhf_(float x)
{
    return 1.0f - 2.0f / (__expf(2.0f * x) + 1.0f);
}

// ---------------- packed f32x2 helpers (sm_100+: 2x fp32 FMA rate) --------
__device__ __forceinline__ unsigned long long pack_dup(float x)
{
    unsigned long long r;
    unsigned u = __float_as_uint(x);
    asm("mov.b64 %0, {%1, %2};" : "=l"(r) : "r"(u), "r"(u));
    return r;
}
__device__ __forceinline__ void fma2(unsigned long long& d,
                                     unsigned long long a, unsigned long long b)
{
    asm("fma.rn.f32x2 %0, %1, %2, %0;" : "+l"(d) : "l"(a), "l"(b));
}
__device__ __forceinline__ float lo32(unsigned long long v)
{
    unsigned l, h;
    asm("mov.b64 {%0, %1}, %2;" : "=r"(l), "=r"(h) : "l"(v));
    return __uint_as_float(l);
}
__device__ __forceinline__ float hi32(unsigned long long v)
{
    unsigned l, h;
    asm("mov.b64 {%0, %1}, %2;" : "=r"(l), "=r"(h) : "l"(v));
    return __uint_as_float(h);
}

// ---------------- cp.async helpers ----------------
__device__ __forceinline__ void cp_async16(uint32_t smem_addr, const void* gptr)
{
    asm volatile("cp.async.cg.shared.global [%0], [%1], 16;"
                 :: "r"(smem_addr), "l"(gptr) : "memory");
}
__device__ __forceinline__ void cp_commit()
{
    asm volatile("cp.async.commit_group;" ::: "memory");
}
template<int N> __device__ __forceinline__ void cp_wait()
{
    asm volatile("cp.async.wait_group %0;" :: "n"(N) : "memory");
}
__device__ __forceinline__ uint32_t smem_u32(const void* p)
{
    return (uint32_t)__cvta_generic_to_shared(p);
}

// ---------------- pack weights into fused [K][4H] layout ----------------
__global__ void pack_kernel(
    const float* __restrict__ wxi, const float* __restrict__ whi, const float* __restrict__ bi,
    const float* __restrict__ wxf, const float* __restrict__ whf, const float* __restrict__ bff,
    const float* __restrict__ wxo, const float* __restrict__ who, const float* __restrict__ bo,
    const float* __restrict__ wxc, const float* __restrict__ whc, const float* __restrict__ bc)
{
    int idx = blockIdx.x * blockDim.x + threadIdx.x;
    if (idx >= Dd * Hh) return;
    int d = idx >> 9;
    int h = idx & 511;
    const float* wx[4] = {wxi, wxf, wxo, wxc};
    const float* wh[4] = {whi, whf, who, whc};
    const float* bs[4] = {bi,  bff, bo,  bc};
#pragma unroll
    for (int g = 0; g < 4; g++) {
        g_Wx[d * G4 + g * Hh + h] = wx[g][idx];
        g_Wh[d * G4 + g * Hh + h] = wh[g][idx];
    }
    if (d == 0) {
#pragma unroll
        for (int g = 0; g < 4; g++) g_bias[g * Hh + h] = bs[g][h];
    }
}

// ---------------- phase 1: Xg = X @ Wx + b  (SGEMM 32768x2048x512) -------
#define BM 128
#define BN 128
#define BK 16

__global__ void __launch_bounds__(256, 2) xg_gemm(const float* __restrict__ A)
{
    __shared__ float As[2][BK][BM];
    __shared__ float Bs[2][BK][BN];
    const int tid  = threadIdx.x;
    const int bx   = blockIdx.x;
    const int by   = blockIdx.y;
    const int row0 = by * BM;
    const int col0 = bx * BN;

    const int tx = tid & 15;
    const int ty = tid >> 4;

    const int i0 = tid * 2;
    const int i1 = tid * 2 + 1;
    const int a_ar0 = i0 >> 2, a_ac0 = (i0 & 3) * 4;
    const int a_ar1 = i1 >> 2, a_ac1 = (i1 & 3) * 4;
    const int b_br0 = i0 >> 5, b_bc0 = (i0 & 31) * 4;
    const int b_br1 = i1 >> 5, b_bc1 = (i1 & 31) * 4;

    float4 av0, av1, bv0, bv1;
    av0 = *(const float4*)&A[(size_t)(row0 + a_ar0) * Dd + a_ac0];
    av1 = *(const float4*)&A[(size_t)(row0 + a_ar1) * Dd + a_ac1];
    bv0 = *(const float4*)&g_Wx[(size_t)b_br0 * G4 + col0 + b_bc0];
    bv1 = *(const float4*)&g_Wx[(size_t)b_br1 * G4 + col0 + b_bc1];
    As[0][a_ac0+0][a_ar0] = av0.x; As[0][a_ac0+1][a_ar0] = av0.y;
    As[0][a_ac0+2][a_ar0] = av0.z; As[0][a_ac0+3][a_ar0] = av0.w;
    As[0][a_ac1+0][a_ar1] = av1.x; As[0][a_ac1+1][a_ar1] = av1.y;
    As[0][a_ac1+2][a_ar1] = av1.z; As[0][a_ac1+3][a_ar1] = av1.w;
    *(float4*)&Bs[0][b_br0][b_bc0] = bv0;
    *(float4*)&Bs[0][b_br1][b_bc1] = bv1;
    __syncthreads();

    // packed accumulators: acc2[i][j2] holds columns (2*j2, 2*j2+1)
    unsigned long long acc2[8][4];
#pragma unroll
    for (int i = 0; i < 8; i++)
#pragma unroll
        for (int j = 0; j < 4; j++) acc2[i][j] = 0ull;

    const int NKT = Dd / BK;   // 32
    for (int kt = 0; kt < NKT; kt++) {
        const int cur = kt & 1, nxt = cur ^ 1;
        if (kt + 1 < NKT) {
            const int k0 = (kt + 1) * BK;
            av0 = *(const float4*)&A[(size_t)(row0 + a_ar0) * Dd + k0 + a_ac0];
            av1 = *(const float4*)&A[(size_t)(row0 + a_ar1) * Dd + k0 + a_ac1];
            bv0 = *(const float4*)&g_Wx[(size_t)(k0 + b_br0) * G4 + col0 + b_bc0];
            bv1 = *(const float4*)&g_Wx[(size_t)(k0 + b_br1) * G4 + col0 + b_bc1];
        }
#pragma unroll
        for (int k = 0; k < BK; k++) {
            float4 a0 = *(const float4*)&As[cur][k][ty * 4];
            float4 a1 = *(const float4*)&As[cur][k][64 + ty * 4];
            ulonglong2 bp0 = *(const ulonglong2*)&Bs[cur][k][tx * 4];
            ulonglong2 bp1 = *(const ulonglong2*)&Bs[cur][k][64 + tx * 4];
            const unsigned long long pb[4] = {bp0.x, bp0.y, bp1.x, bp1.y};
            const float ra[8] = {a0.x, a0.y, a0.z, a0.w, a1.x, a1.y, a1.z, a1.w};
#pragma unroll
            for (int i = 0; i < 8; i++) {
                const unsigned long long pa = pack_dup(ra[i]);
#pragma unroll
                for (int j = 0; j < 4; j++)
                    fma2(acc2[i][j], pa, pb[j]);
            }
        }
        if (kt + 1 < NKT) {
            As[nxt][a_ac0+0][a_ar0] = av0.x; As[nxt][a_ac0+1][a_ar0] = av0.y;
            As[nxt][a_ac0+2][a_ar0] = av0.z; As[nxt][a_ac0+3][a_ar0] = av0.w;
            As[nxt][a_ac1+0][a_ar1] = av1.x; As[nxt][a_ac1+1][a_ar1] = av1.y;
            As[nxt][a_ac1+2][a_ar1] = av1.z; As[nxt][a_ac1+3][a_ar1] = av1.w;
            *(float4*)&Bs[nxt][b_br0][b_bc0] = bv0;
            *(float4*)&Bs[nxt][b_br1][b_bc1] = bv1;
            __syncthreads();
        }
    }

    // epilogue: add bias, remap row r=(b*512+t) -> Xg row (t*64+b)
#pragma unroll
    for (int i = 0; i < 8; i++) {
        const int mr  = row0 + ((i < 4) ? (ty * 4 + i) : (64 + ty * 4 + (i - 4)));
        const int orow = (mr & (Tt - 1)) * Bsz + (mr >> 9);
#pragma unroll
        for (int jh = 0; jh < 2; jh++) {
            const int c = col0 + jh * 64 + tx * 4;
            float4 bv = *(const float4*)&g_bias[c];
            float4 v;
            v.x = lo32(acc2[i][jh * 2 + 0]) + bv.x;
            v.y = hi32(acc2[i][jh * 2 + 0]) + bv.y;
            v.z = lo32(acc2[i][jh * 2 + 1]) + bv.z;
            v.w = hi32(acc2[i][jh * 2 + 1]) + bv.w;
            *(float4*)&g_Xg[(size_t)orow * G4 + c] = v;
        }
    }
}

// ---------------- phase 2: persistent recurrence kernel ----------------
// 128 CTAs x 256 threads, CTA owns 4 hidden cols (16 gate cols).
// Warp w (=ks) consumes only h rows [64w, 64w+64): per-warp cp.async pipeline
// stages its 16KB chunk in 4 sub-chunks, overlapped with the FMA stream.
// Inner product uses packed fma.rn.f32x2: batch pairs packed (free from SMEM),
// weights dup-packed -> FMA floor per step halves (8192 -> 4096 cyc).
#define SMEM_W_FLOATS   (512 * 16)          // 32 KB
#define SMEM_H_FLOATS   (512 * 64)          // 128 KB (8 warp regions of 16KB)
#define SMEM_RED_FLOATS (8 * 32 * 33)       // 33.8 KB (33-skew, scalar access)
#define SMEM_XG_FLOATS  (64 * 16)           // 4 KB
#define SMEM_OUT_FLOATS (64 * 4)            // 1 KB
#define REC_SMEM_BYTES  ((SMEM_W_FLOATS + SMEM_H_FLOATS + SMEM_RED_FLOATS + \
                          SMEM_XG_FLOATS + SMEM_OUT_FLOATS) * 4)

__global__ void __launch_bounds__(256, 1) lstm_rec(float* __restrict__ out)
{
    extern __shared__ float sm[];
    float* sh_w   = sm;                              // [512][16], cc = jj*4+gate
    float* sh_h   = sm + SMEM_W_FLOATS;              // 8 x [64 k'][64 b]
    float* sh_red = sh_h + SMEM_H_FLOATS;            // [(ks*32+lane)][33]
    float* sh_xg  = sh_red + SMEM_RED_FLOATS;        // [64 b][16 = gate*4+jj]
    float* sh_out = sh_xg + SMEM_XG_FLOATS;          // [64 b][4 jj]

    const int tid  = threadIdx.x;
    const int cta  = blockIdx.x;
    const int j0   = cta * 4;
    const int lane = tid & 31;

    // load persistent W_h slice (once)
    for (int i = tid; i < 512 * 16; i += 256) {
        const int k = i >> 4, cc = i & 15;
        const int jj = cc >> 2, gate = cc & 3;
        sh_w[i] = g_Wh[(size_t)k * G4 + gate * Hh + j0 + jj];
    }

    // GEMM thread decomposition: warp ks owns K chunk [ks*64, ks*64+64)
    const int ks   = tid >> 5;        // 0..7 (= warp id)
    const int bg   = lane >> 2;       // 0..7  -> b0 = bg*8
    const int cg   = lane & 3;        // jj group (4 gate cols)
    const int kb   = ks * 64;

    // this warp's SMEM h region
    float*         sh_hw  = sh_h + ks * (64 * 64);
    const uint32_t dst0   = smem_u32(sh_hw);

    // epilogue decomposition: thread <-> (batch, hidden col)
    const int e_b    = tid & 63;
    const int e_jj   = tid >> 6;      // 0..3
    const int e_bg   = e_b >> 3, e_bb = e_b & 7;
    const int e_base = e_bg * 4 + e_jj;
    const int jcol   = j0 + e_jj;

    float c_state = 0.f;

    // ---- step 0: h = 0, so g = Xg[0] only ----
    {
        float gg[4];
#pragma unroll
        for (int gate = 0; gate < 4; gate++)
            gg[gate] = g_Xg[(size_t)e_b * G4 + gate * Hh + jcol];
        const float I = sigmoidf_(gg[0]);
        const float F = sigmoidf_(gg[1]);
        const float O = sigmoidf_(gg[2]);
        const float Cd = tanhf_(gg[3]);
        c_state = F * c_state + I * Cd;
        const float hval = O * tanhf_(c_state);
        g_hbuf[0][jcol * Bsz + e_b] = hval;
        sh_out[e_b * 4 + e_jj] = hval;
    }
    __syncthreads();
    if (tid < 64)
        *(float4*)&out[(size_t)tid * (Tt * Hh) + j0] = *(const float4*)&sh_out[tid * 4];
    grid_barrier();

    const float4* sh_w4 = (const float4*)sh_w;

    for (int t = 1; t < Tt; t++) {
        // ---- Xg prefetch: coalesced float4 loads, redistributed via SMEM ----
        float4 xg4[4];
        if (tid < 64) {
#pragma unroll
            for (int g = 0; g < 4; g++)
                xg4[g] = __ldg((const float4*)&g_Xg[((size_t)t * Bsz + tid) * G4 +
                                                    g * Hh + j0]);
        }

        // ---- warp-local cp.async pipeline: 4 sub-chunks of 4KB ----
        const float* hsrc = g_hbuf[(t + 1) & 1] + kb * 64;
#pragma unroll
        for (int j = 0; j < 8; j++)
            cp_async16(dst0 + (j * 32 + lane) * 16, hsrc + (j * 32 + lane) * 4);
        cp_commit();
#pragma unroll
        for (int j = 8; j < 16; j++)
            cp_async16(dst0 + (j * 32 + lane) * 16, hsrc + (j * 32 + lane) * 4);
        cp_commit();

        // packed accumulators: acc2[b2][c] holds batches (bg*8+2*b2, +1)
        unsigned long long acc2[4][4];
#pragma unroll
        for (int b = 0; b < 4; b++)
#pragma unroll
            for (int c = 0; c < 4; c++) acc2[b][c] = 0ull;

#pragma unroll
        for (int s = 0; s < 4; s++) {
            if (s < 2) {
                const int jb = (s + 2) * 8;
#pragma unroll
                for (int j = 0; j < 8; j++)
                    cp_async16(dst0 + ((jb + j) * 32 + lane) * 16,
                               hsrc + ((jb + j) * 32 + lane) * 4);
                cp_commit();
            }
            if      (s == 0) cp_wait<2>();
            else if (s == 1) cp_wait<2>();
            else if (s == 2) cp_wait<1>();
            else             cp_wait<0>();
            __syncwarp();

#pragma unroll
            for (int kk = 0; kk < 16; kk++) {
                const int kl = s * 16 + kk;          // local k in warp chunk
                const float4 w  = sh_w4[(kb + kl) * 4 + cg];
                ulonglong2 hp0 = *(const ulonglong2*)&sh_hw[kl * 64 + bg * 8];
                ulonglong2 hp1 = *(const ulonglong2*)&sh_hw[kl * 64 + bg * 8 + 4];
                const unsigned long long ph[4] = {hp0.x, hp0.y, hp1.x, hp1.y};
                const unsigned long long pw[4] = {pack_dup(w.x), pack_dup(w.y),
                                                  pack_dup(w.z), pack_dup(w.w)};
#pragma unroll
                for (int b = 0; b < 4; b++)
#pragma unroll
                    for (int c = 0; c < 4; c++)
                        fma2(acc2[b][c], ph[b], pw[c]);
            }
        }

        // write partials — SCALAR stores into 33-skewed rows (conflict-free;
        // 132B row stride is NOT 16B-aligned, so no float4 here)
        float* myred = &sh_red[(ks * 32 + lane) * 33];
#pragma unroll
        for (int b = 0; b < 4; b++)
#pragma unroll
            for (int c = 0; c < 4; c++) {
                myred[(2 * b)     * 4 + c] = lo32(acc2[b][c]);
                myred[(2 * b + 1) * 4 + c] = hi32(acc2[b][c]);
            }
        // park prefetched Xg in SMEM for the epilogue threads
        if (tid < 64) {
#pragma unroll
            for (int g = 0; g < 4; g++)
                *(float4*)&sh_xg[tid * 16 + g * 4] = xg4[g];
        }
        __syncthreads();

        // reduce 8 K-partials + Xg, then gate math: thread owns (e_b, jcol)
        float gg[4];
#pragma unroll
        for (int gate = 0; gate < 4; gate++) {
            float ss = sh_xg[e_b * 16 + gate * 4 + e_jj];
#pragma unroll
            for (int p = 0; p < 8; p++)
                ss += sh_red[(p * 32 + e_base) * 33 + e_bb * 4 + gate];
            gg[gate] = ss;
        }
        const float I = sigmoidf_(gg[0]);
        const float F = sigmoidf_(gg[1]);
        const float O = sigmoidf_(gg[2]);
        const float Cd = tanhf_(gg[3]);
        c_state = F * c_state + I * Cd;
        const float hval = O * tanhf_(c_state);
        g_hbuf[t & 1][jcol * Bsz + e_b] = hval;   // coalesced along batch
        sh_out[e_b * 4 + e_jj] = hval;
        __syncthreads();
        if (tid < 64)
            *(float4*)&out[(size_t)tid * (Tt * Hh) + (size_t)t * Hh + j0] =
                *(const float4*)&sh_out[tid * 4];

        grid_barrier();
    }
}

// ---------------- launch ----------------
extern "C" void kernel_launch(void* const* d_in, const int* in_sizes, int n_in,
                              void* d_out, int out_size)
{
    const float* X   = (const float*)d_in[0];
    const float* wxi = (const float*)d_in[1];
    const float* whi = (const float*)d_in[2];
    const float* bi  = (const float*)d_in[3];
    const float* wxf = (const float*)d_in[4];
    const float* whf = (const float*)d_in[5];
    const float* bff = (const float*)d_in[6];
    const float* wxo = (const float*)d_in[7];
    const float* who = (const float*)d_in[8];
    const float* bo  = (const float*)d_in[9];
    const float* wxc = (const float*)d_in[10];
    const float* whc = (const float*)d_in[11];
    const float* bc  = (const float*)d_in[12];
    float* out = (float*)d_out;

    pack_kernel<<<(Dd * Hh + 255) / 256, 256>>>(wxi, whi, bi, wxf, whf, bff,
                                                wxo, who, bo, wxc, whc, bc);

    dim3 grid(G4 / BN, (Bsz * Tt) / BM);   // (16, 256)
    xg_gemm<<<grid, 256>>>(X);

    cudaFuncSetAttribute(lstm_rec, cudaFuncAttributeMaxDynamicSharedMemorySize,
                         REC_SMEM_BYTES);
    lstm_rec<<<NCTA, 256, REC_SMEM_BYTES>>>(out);
}